// round 10
// baseline (speedup 1.0000x reference)
#include <cuda_runtime.h>

// CrossAttention with seqlen-1 K/V broadcast:
//   out[b,t,:] = (visual_features[b] @ Wv + bv) @ Wp + bp   for every t.
// Softmax over T identical logits is exactly uniform; averaging T identical
// value rows returns the row. x/Wq/Wk are mathematically irrelevant.
//
// 3 graph nodes (no grid barriers — launch boundaries are cheaper):
//   1) gemm1:  g_part[sp]  = partial(vf @ Wv)            grid(8,32)x128
//   2) gemm2:  z reduce (+bv) prologue, then
//              g_part2[sp] = partial(z @ Wp), SPLITK2=4  grid(8,4)x128
//   3) bcast:  per-thread reduce of 4 partials (+bp),
//              then broadcast-store over T               grid(512)x256

#define CC 1024
#define BB 4
#define TT_TOTAL 1024
#define SPLITK1 32
#define KCH1 (CC / SPLITK1)   // 32
#define SPLITK2 4
#define KCH2 (CC / SPLITK2)   // 256

__device__ float g_part [SPLITK1][BB * CC];  // partials of vf@Wv
__device__ float g_part2[SPLITK2][BB * CC];  // partials of z@Wp

// ---------------------------------------------------------------------------
// Kernel 1: partial GEMM  g_part[sp][b*C+j] = sum_{i in chunk} vf[b][i]*Wv[i][j]
__global__ void __launch_bounds__(128)
gemm1_kernel(const float* __restrict__ vf,   // [BB][CC]
             const float* __restrict__ W)    // Wv [CC][CC]
{
    __shared__ float s_in[BB][KCH1];
    const int tid = threadIdx.x;             // 0..127
    const int j   = blockIdx.x * 128 + tid;
    const int k0  = blockIdx.y * KCH1;

    {   // 128 threads <-> BB*KCH1 = 128 inputs
        int b = tid >> 5, i = tid & 31;
        s_in[b][i] = vf[b * CC + k0 + i];
    }
    __syncthreads();

    float a0 = 0.f, a1 = 0.f, a2 = 0.f, a3 = 0.f;
    const float* __restrict__ Wc = W + (size_t)k0 * CC + j;
    #pragma unroll
    for (int i = 0; i < KCH1; i++) {
        float wv = Wc[(size_t)i * CC];
        a0 += s_in[0][i] * wv;
        a1 += s_in[1][i] * wv;
        a2 += s_in[2][i] * wv;
        a3 += s_in[3][i] * wv;
    }
    float* p = &g_part[blockIdx.y][0];
    p[0 * CC + j] = a0;
    p[1 * CC + j] = a1;
    p[2 * CC + j] = a2;
    p[3 * CC + j] = a3;
}

// ---------------------------------------------------------------------------
// Kernel 2: z-slice reduce (+bv) prologue, then partial(z @ Wp) with SPLITK2=4.
// grid = (8, 4) x 128 threads; each block covers 128 j-columns, 256 K-rows.
__global__ void __launch_bounds__(128)
gemm2_kernel(const float* __restrict__ bv,
             const float* __restrict__ W)    // Wp [CC][CC]
{
    __shared__ float s_z[BB][KCH2];          // 4 KB
    const int tid = threadIdx.x;             // 0..127
    const int j   = blockIdx.x * 128 + tid;
    const int k0  = blockIdx.y * KCH2;

    // reduce the z slice this block needs: BB*KCH2 = 1024 values, 8 per thread
    for (int idx = tid; idx < BB * KCH2; idx += 128) {
        int b = idx >> 8, i = idx & (KCH2 - 1);
        float s = bv[k0 + i];
        #pragma unroll
        for (int sp = 0; sp < SPLITK1; sp++)
            s += g_part[sp][b * CC + k0 + i];
        s_z[b][i] = s;
    }
    __syncthreads();

    float a0 = 0.f, a1 = 0.f, a2 = 0.f, a3 = 0.f;
    const float* __restrict__ Wc = W + (size_t)k0 * CC + j;
    #pragma unroll 8
    for (int i = 0; i < KCH2; i++) {
        float wv = Wc[(size_t)i * CC];
        a0 += s_z[0][i] * wv;
        a1 += s_z[1][i] * wv;
        a2 += s_z[2][i] * wv;
        a3 += s_z[3][i] * wv;
    }
    float* p = &g_part2[blockIdx.y][0];
    p[0 * CC + j] = a0;
    p[1 * CC + j] = a1;
    p[2 * CC + j] = a2;
    p[3 * CC + j] = a3;
}

// ---------------------------------------------------------------------------
// Kernel 3: fused wred + broadcast. 512 blocks x 256 threads.
// Each thread: w4 = bp4 + sum of 4 partial float4s, then 8 STG.128 rows.
#define ROWS_PER_BLK 8
__global__ void __launch_bounds__(256)
bcast_kernel(const float* __restrict__ bp,
             float* __restrict__ out)        // [BB][T][CC]
{
    const int b  = blockIdx.x >> 7;                          // 0..3
    const int t0 = (blockIdx.x & 127) * ROWS_PER_BLK;
    const int c4 = threadIdx.x;                              // float4 col index

    float4 w = *(reinterpret_cast<const float4*>(bp) + c4);
    #pragma unroll
    for (int sp = 0; sp < SPLITK2; sp++) {
        float4 pv = *(reinterpret_cast<const float4*>(&g_part2[sp][b * CC]) + c4);
        w.x += pv.x; w.y += pv.y; w.z += pv.z; w.w += pv.w;
    }

    float4* o = reinterpret_cast<float4*>(out + (size_t)(b * TT_TOTAL + t0) * CC) + c4;
    #pragma unroll
    for (int t = 0; t < ROWS_PER_BLK; t++)
        o[(size_t)t * (CC / 4)] = w;
}

extern "C" void kernel_launch(void* const* d_in, const int* in_sizes, int n_in,
                              void* d_out, int out_size)
{
    // metadata order: x, visual_features, Wq, bq, Wk, bk, Wv, bv, Wp, bp
    const float* vf = (const float*)d_in[1];
    const float* Wv = (const float*)d_in[6];
    const float* bv = (const float*)d_in[7];
    const float* Wp = (const float*)d_in[8];
    const float* bp = (const float*)d_in[9];
    float* out = (float*)d_out;

    gemm1_kernel<<<dim3(CC / 128, SPLITK1), 128>>>(vf, Wv);
    gemm2_kernel<<<dim3(CC / 128, SPLITK2), 128>>>(bv, Wp);
    bcast_kernel<<<BB * (TT_TOTAL / ROWS_PER_BLK), 256>>>(bp, out);
}

// round 15
// speedup vs baseline: 1.9533x; 1.9533x over previous
#include <cuda_runtime.h>
#include <cstdint>

// CrossAttention with seqlen-1 K/V broadcast:
//   out[b,t,:] = (visual_features[b] @ Wv + bv) @ Wp + bp   for every t.
// Softmax over T identical logits is exactly uniform; averaging T identical
// value rows returns the row. x/Wq/Wk are mathematically irrelevant.
//
// 4 graph nodes, all built for MLP:
//   1) gemm1: partial(vf @ Wv), float4 loads     grid 128 x 256
//   2) gemm2: z reduce (+bv) + partial(z @ Wp)   grid 128 x 256
//   3) wred:  g_w = bp + sum of 128 partials     grid 128 x 256
//   4) bcast: smem-staged TMA bulk stores        grid 256 x 256

#define CC 1024
#define BB 4
#define TT_TOTAL 1024
#define SP 128
#define KCH (CC / SP)        // 8 K-rows per split block

__device__ float g_part [SP][BB * CC];   // partials of vf@Wv  (2 MB)
__device__ float g_part2[SP][BB * CC];   // partials of z@Wp   (2 MB)
__device__ float g_w[BB * CC];           // final w = z@Wp + bp

// ---------------------------------------------------------------------------
// Kernel 1: g_part[sp][b*CC + j] = sum_{i in chunk} vf[b][i] * Wv[i][j]
// 256 threads x 4 columns = all 1024 columns per block; KCH=8 rows.
// Per thread: 8 x LDG.128 of W (coalesced), 16 accumulators.
__global__ void __launch_bounds__(256)
gemm1_kernel(const float* __restrict__ vf,   // [BB][CC]
             const float* __restrict__ W)    // Wv [CC][CC]
{
    __shared__ float s_in[BB][KCH];
    const int tid = threadIdx.x;
    const int sp  = blockIdx.x;
    const int k0  = sp * KCH;
    const int j0  = tid * 4;

    if (tid < BB * KCH) {                    // 32 values
        int b = tid >> 3, i = tid & 7;
        s_in[b][i] = vf[b * CC + k0 + i];
    }
    __syncthreads();

    float4 acc[BB] = {};
    const float4* __restrict__ Wc =
        reinterpret_cast<const float4*>(W + (size_t)k0 * CC + j0);
    #pragma unroll
    for (int i = 0; i < KCH; i++) {
        float4 w = Wc[(size_t)i * (CC / 4)];
        #pragma unroll
        for (int b = 0; b < BB; b++) {
            float s = s_in[b][i];
            acc[b].x += s * w.x; acc[b].y += s * w.y;
            acc[b].z += s * w.z; acc[b].w += s * w.w;
        }
    }
    #pragma unroll
    for (int b = 0; b < BB; b++)
        *reinterpret_cast<float4*>(&g_part[sp][b * CC + j0]) = acc[b];
}

// ---------------------------------------------------------------------------
// Kernel 2: z-slice reduce (+bv) prologue, then partial(z @ Wp), same shape.
__global__ void __launch_bounds__(256)
gemm2_kernel(const float* __restrict__ bv,
             const float* __restrict__ W)    // Wp [CC][CC]
{
    __shared__ float s_red[8][32];
    __shared__ float s_z[BB][KCH];
    const int tid = threadIdx.x;
    const int sp  = blockIdx.x;
    const int k0  = sp * KCH;
    const int j0  = tid * 4;

    // Reduce z slice: 32 (b,i) pairs x 128 partials.
    // Coalesced: consecutive threads -> consecutive (b,i); 8 groups x 16 sp.
    {
        const int p = tid & 31, g = tid >> 5;
        const int b = p >> 3,  i = p & 7;
        float s = 0.f;
        #pragma unroll
        for (int u = 0; u < 16; u++)
            s += g_part[g * 16 + u][b * CC + k0 + i];
        s_red[g][p] = s;
    }
    __syncthreads();
    if (tid < 32) {
        int b = tid >> 3, i = tid & 7;
        float z = bv[k0 + i];
        #pragma unroll
        for (int g = 0; g < 8; g++) z += s_red[g][tid];
        s_z[b][i] = z;
    }
    __syncthreads();

    float4 acc[BB] = {};
    const float4* __restrict__ Wc =
        reinterpret_cast<const float4*>(W + (size_t)k0 * CC + j0);
    #pragma unroll
    for (int i = 0; i < KCH; i++) {
        float4 w = Wc[(size_t)i * (CC / 4)];
        #pragma unroll
        for (int b = 0; b < BB; b++) {
            float s = s_z[b][i];
            acc[b].x += s * w.x; acc[b].y += s * w.y;
            acc[b].z += s * w.z; acc[b].w += s * w.w;
        }
    }
    #pragma unroll
    for (int b = 0; b < BB; b++)
        *reinterpret_cast<float4*>(&g_part2[sp][b * CC + j0]) = acc[b];
}

// ---------------------------------------------------------------------------
// Kernel 3: g_w[e] = bp[e & 1023] + sum_{sp<128} g_part2[sp][e]
// 128 blocks x 256 thr; block covers 32 elements, 8 sp-groups of 16.
__global__ void __launch_bounds__(256)
wred_kernel(const float* __restrict__ bp)
{
    __shared__ float s[8][32];
    const int e0 = blockIdx.x * 32;
    const int e  = threadIdx.x & 31, g = threadIdx.x >> 5;

    float r = 0.f;
    #pragma unroll
    for (int u = 0; u < 16; u++)
        r += g_part2[g * 16 + u][e0 + e];
    s[g][e] = r;
    __syncthreads();
    if (threadIdx.x < 32) {
        float w = bp[(e0 + threadIdx.x) & (CC - 1)];
        #pragma unroll
        for (int g2 = 0; g2 < 8; g2++) w += s[g2][threadIdx.x];
        g_w[e0 + threadIdx.x] = w;
    }
}

// ---------------------------------------------------------------------------
// Kernel 4: broadcast via TMA bulk stores. 256 blocks x 256 thr.
// Block: b = bid>>6, 16 rows. Stage the 4 KB row in smem once, then one
// thread issues 16 x cp.async.bulk (SMEM -> GMEM), bypassing the STG pipe.
#define ROWS_PER_BLK 16
__global__ void __launch_bounds__(256)
bcast_kernel(float* __restrict__ out)        // [BB][T][CC]
{
    __shared__ __align__(16) float s_row[CC];
    const int b  = blockIdx.x >> 6;
    const int t0 = (blockIdx.x & 63) * ROWS_PER_BLK;

    reinterpret_cast<float4*>(s_row)[threadIdx.x] =
        reinterpret_cast<const float4*>(&g_w[b * CC])[threadIdx.x];
    __syncthreads();
    asm volatile("fence.proxy.async.shared::cta;" ::: "memory");

    if (threadIdx.x == 0) {
        uint32_t saddr;
        asm("{ .reg .u64 t; cvta.to.shared.u64 t, %1; cvt.u32.u64 %0, t; }"
            : "=r"(saddr) : "l"(s_row));
        float* dst = out + (size_t)(b * TT_TOTAL + t0) * CC;
        #pragma unroll
        for (int t = 0; t < ROWS_PER_BLK; t++) {
            asm volatile(
                "cp.async.bulk.global.shared::cta.bulk_group [%0], [%1], %2;"
                :: "l"(dst + (size_t)t * CC), "r"(saddr), "r"(CC * 4u)
                : "memory");
        }
        asm volatile("cp.async.bulk.commit_group;" ::: "memory");
        asm volatile("cp.async.bulk.wait_group 0;" ::: "memory");
    }
}

extern "C" void kernel_launch(void* const* d_in, const int* in_sizes, int n_in,
                              void* d_out, int out_size)
{
    // metadata order: x, visual_features, Wq, bq, Wk, bk, Wv, bv, Wp, bp
    const float* vf = (const float*)d_in[1];
    const float* Wv = (const float*)d_in[6];
    const float* bv = (const float*)d_in[7];
    const float* Wp = (const float*)d_in[8];
    const float* bp = (const float*)d_in[9];
    float* out = (float*)d_out;

    gemm1_kernel<<<SP, 256>>>(vf, Wv);
    gemm2_kernel<<<SP, 256>>>(bv, Wp);
    wred_kernel<<<(BB * CC) / 32, 256>>>(bp);
    bcast_kernel<<<BB * (TT_TOTAL / ROWS_PER_BLK), 256>>>(out);
}